// round 3
// baseline (speedup 1.0000x reference)
#include <cuda_runtime.h>
#include <cuda_bf16.h>
#include <cstdint>
#include <math.h>

// Problem dims (fixed by the reference)
#define TDIM 4096
#define CDIM 2048
#define NF   2048
#define N3   6144   // 3*NF

#define BM 128
#define BN 128
#define BK 32
#define SA 36    // A-style tile stride in floats ([row][k]), conflict-free
#define SB 136   // B NN tile stride in floats ([k][n]), conflict-free

// Scratch: qkv (T x 3NF) and P (T x T), both fp32.
__device__ __align__(256) float g_qkv[(size_t)TDIM * N3];   // 96 MB
__device__ __align__(256) float g_P[(size_t)TDIM * TDIM];   // 64 MB

__device__ __forceinline__ uint32_t f2tf32(float x) {
    uint32_t u;
    asm("cvt.rna.tf32.f32 %0, %1;" : "=r"(u) : "f"(x));
    return u;
}

__device__ __forceinline__ void mma_tf32(float* d,
    uint32_t a0, uint32_t a1, uint32_t a2, uint32_t a3,
    uint32_t b0, uint32_t b1)
{
    asm volatile(
        "mma.sync.aligned.m16n8k8.row.col.f32.tf32.tf32.f32 "
        "{%0,%1,%2,%3}, {%4,%5,%6,%7}, {%8,%9}, {%0,%1,%2,%3};\n"
        : "+f"(d[0]), "+f"(d[1]), "+f"(d[2]), "+f"(d[3])
        : "r"(a0), "r"(a1), "r"(a2), "r"(a3), "r"(b0), "r"(b1));
}

__device__ __forceinline__ void cp16(float* smem_dst, const float* gsrc) {
    uint32_t s = (uint32_t)__cvta_generic_to_shared(smem_dst);
    asm volatile("cp.async.cg.shared.global [%0], [%1], 16;\n" :: "r"(s), "l"(gsrc));
}
#define CP_COMMIT() asm volatile("cp.async.commit_group;\n")
#define CP_WAIT0()  asm volatile("cp.async.wait_group 0;\n")

// Async-copy a 128x32 fp32 tile (row pitch ld) into tile[row][k], stride SA.
__device__ __forceinline__ void loadA_async(float* tile, const float* __restrict__ src,
                                            size_t ld, int tid)
{
    #pragma unroll
    for (int i = 0; i < 4; i++) {
        int idx = tid + i * 256;
        int r = idx >> 3;
        int k = (idx & 7) << 2;
        cp16(tile + r * SA + k, src + (size_t)r * ld + k);
    }
}

// Async-copy a 32x128 fp32 tile (row pitch ld) into tile[k][n], stride SB.
__device__ __forceinline__ void loadB_async(float* tile, const float* __restrict__ src,
                                            size_t ld, int tid)
{
    #pragma unroll
    for (int i = 0; i < 4; i++) {
        int idx = tid + i * 256;
        int k = idx >> 5;
        int n = (idx & 31) << 2;
        cp16(tile + k * SB + n, src + (size_t)k * ld + n);
    }
}

// Compute one 128x128x32 tile step; B tile stored [k][n] stride SB (NN case).
__device__ __forceinline__ void compute_NN(const float* As, const float* Bs,
                                           float (*acc)[4], int wm, int wn, int g, int t4)
{
    #pragma unroll
    for (int ks = 0; ks < 4; ks++) {
        const int kb = ks * 8;
        uint32_t af[4][4], bf[4][2];
        #pragma unroll
        for (int mt = 0; mt < 4; mt++) {
            const int m = wm * 64 + mt * 16 + g;
            af[mt][0] = f2tf32(As[m * SA + kb + t4]);
            af[mt][1] = f2tf32(As[(m + 8) * SA + kb + t4]);
            af[mt][2] = f2tf32(As[m * SA + kb + t4 + 4]);
            af[mt][3] = f2tf32(As[(m + 8) * SA + kb + t4 + 4]);
        }
        #pragma unroll
        for (int nt = 0; nt < 4; nt++) {
            const int n = wn * 32 + nt * 8 + g;
            bf[nt][0] = f2tf32(Bs[(kb + t4) * SB + n]);
            bf[nt][1] = f2tf32(Bs[(kb + t4 + 4) * SB + n]);
        }
        #pragma unroll
        for (int mt = 0; mt < 4; mt++)
            #pragma unroll
            for (int nt = 0; nt < 4; nt++)
                mma_tf32(acc[mt * 4 + nt],
                         af[mt][0], af[mt][1], af[mt][2], af[mt][3],
                         bf[nt][0], bf[nt][1]);
    }
}

// Compute one tile step; B tile stored [n][k] stride SA (NT case, K rows).
__device__ __forceinline__ void compute_NT(const float* As, const float* Ks,
                                           float (*acc)[4], int wm, int wn, int g, int t4)
{
    #pragma unroll
    for (int ks = 0; ks < 4; ks++) {
        const int kb = ks * 8;
        uint32_t af[4][4], bf[4][2];
        #pragma unroll
        for (int mt = 0; mt < 4; mt++) {
            const int m = wm * 64 + mt * 16 + g;
            af[mt][0] = f2tf32(As[m * SA + kb + t4]);
            af[mt][1] = f2tf32(As[(m + 8) * SA + kb + t4]);
            af[mt][2] = f2tf32(As[m * SA + kb + t4 + 4]);
            af[mt][3] = f2tf32(As[(m + 8) * SA + kb + t4 + 4]);
        }
        #pragma unroll
        for (int nt = 0; nt < 4; nt++) {
            const int n = wn * 32 + nt * 8 + g;
            bf[nt][0] = f2tf32(Ks[n * SA + kb + t4]);
            bf[nt][1] = f2tf32(Ks[n * SA + kb + t4 + 4]);
        }
        #pragma unroll
        for (int mt = 0; mt < 4; mt++)
            #pragma unroll
            for (int nt = 0; nt < 4; nt++)
                mma_tf32(acc[mt * 4 + nt],
                         af[mt][0], af[mt][1], af[mt][2], af[mt][3],
                         bf[nt][0], bf[nt][1]);
    }
}

// ---------------------------------------------------------------------------
// Kernel 1: qkv = x @ W + b   (NN), 2-stage cp.async pipeline
// ---------------------------------------------------------------------------
__global__ __launch_bounds__(256, 2)
void k_gemm_qkv(const float* __restrict__ A,
                const float* __restrict__ B,
                const float* __restrict__ bias)
{
    extern __shared__ float sm[];
    float* As[2] = { sm,               sm + BM * SA };
    float* Bs[2] = { sm + 2 * BM * SA, sm + 2 * BM * SA + BK * SB };

    const int tid = threadIdx.x;
    const int lane = tid & 31, wid = tid >> 5;
    const int wm = wid & 1, wn = wid >> 1;
    const int g = lane >> 2, t4 = lane & 3;
    const int m0 = blockIdx.y * BM;
    const int n0 = blockIdx.x * BN;

    float acc[16][4];
    #pragma unroll
    for (int i = 0; i < 16; i++)
        #pragma unroll
        for (int j = 0; j < 4; j++) acc[i][j] = 0.f;

    const int nk = CDIM / BK;
    loadA_async(As[0], A + (size_t)m0 * CDIM, CDIM, tid);
    loadB_async(Bs[0], B + n0, N3, tid);
    CP_COMMIT();

    int buf = 0;
    for (int it = 0; it < nk; it++) {
        CP_WAIT0();
        __syncthreads();
        if (it + 1 < nk) {
            const int kn = (it + 1) * BK;
            loadA_async(As[buf ^ 1], A + (size_t)m0 * CDIM + kn, CDIM, tid);
            loadB_async(Bs[buf ^ 1], B + (size_t)kn * N3 + n0, N3, tid);
            CP_COMMIT();
        }
        compute_NN(As[buf], Bs[buf], acc, wm, wn, g, t4);
        buf ^= 1;
    }

    #pragma unroll
    for (int mt = 0; mt < 4; mt++) {
        #pragma unroll
        for (int nt = 0; nt < 4; nt++) {
            const int row = m0 + wm * 64 + mt * 16 + g;
            const int col = n0 + wn * 32 + nt * 8 + t4 * 2;
            const float b0 = bias[col], b1 = bias[col + 1];
            *(float2*)(g_qkv + (size_t)row * N3 + col) =
                make_float2(acc[mt*4+nt][0] + b0, acc[mt*4+nt][1] + b1);
            *(float2*)(g_qkv + (size_t)(row + 8) * N3 + col) =
                make_float2(acc[mt*4+nt][2] + b0, acc[mt*4+nt][3] + b1);
        }
    }
}

// ---------------------------------------------------------------------------
// Kernel 2: S = scale * Q @ K^T (NT), masked-block skipping, 2-stage pipeline
// ---------------------------------------------------------------------------
__global__ __launch_bounds__(256, 2)
void k_gemm_s(const int* __restrict__ n_padd_p)
{
    const int np = *n_padd_p;
    const int rm = blockIdx.y * BM;
    const int cn = blockIdx.x * BN;
    if (cn >= rm + BM) return;
    if (cn + BN <= np) return;
    if (rm + BM <= np) return;

    extern __shared__ float sm[];
    float* As[2] = { sm,               sm + BM * SA };
    float* Ks[2] = { sm + 2 * BM * SA, sm + 3 * BM * SA };

    const int tid = threadIdx.x;
    const int lane = tid & 31, wid = tid >> 5;
    const int wm = wid & 1, wn = wid >> 1;
    const int g = lane >> 2, t4 = lane & 3;

    float acc[16][4];
    #pragma unroll
    for (int i = 0; i < 16; i++)
        #pragma unroll
        for (int j = 0; j < 4; j++) acc[i][j] = 0.f;

    const int nk = NF / BK;
    loadA_async(As[0], g_qkv + (size_t)rm * N3, N3, tid);
    loadA_async(Ks[0], g_qkv + (size_t)cn * N3 + NF, N3, tid);
    CP_COMMIT();

    int buf = 0;
    for (int it = 0; it < nk; it++) {
        CP_WAIT0();
        __syncthreads();
        if (it + 1 < nk) {
            const int kn = (it + 1) * BK;
            loadA_async(As[buf ^ 1], g_qkv + (size_t)rm * N3 + kn, N3, tid);
            loadA_async(Ks[buf ^ 1], g_qkv + (size_t)cn * N3 + NF + kn, N3, tid);
            CP_COMMIT();
        }
        compute_NT(As[buf], Ks[buf], acc, wm, wn, g, t4);
        buf ^= 1;
    }

    const float scale = rsqrtf((float)NF);
    #pragma unroll
    for (int mt = 0; mt < 4; mt++) {
        #pragma unroll
        for (int nt = 0; nt < 4; nt++) {
            const int row = rm + wm * 64 + mt * 16 + g;
            const int col = cn + wn * 32 + nt * 8 + t4 * 2;
            *(float2*)(g_P + (size_t)row * TDIM + col) =
                make_float2(acc[mt*4+nt][0] * scale, acc[mt*4+nt][1] * scale);
            *(float2*)(g_P + (size_t)(row + 8) * TDIM + col) =
                make_float2(acc[mt*4+nt][2] * scale, acc[mt*4+nt][3] * scale);
        }
    }
}

// ---------------------------------------------------------------------------
// Kernel 3: row softmax in-place on g_P.
// ---------------------------------------------------------------------------
__global__ __launch_bounds__(256)
void k_softmax(const int* __restrict__ n_padd_p)
{
    const int r = blockIdx.x;
    const int np = *n_padd_p;
    const int tid = threadIdx.x;
    __shared__ float red[256];

    float* prow = g_P + (size_t)r * TDIM;

    if (r < np) {
        float4 z = make_float4(0.f, 0.f, 0.f, 0.f);
        for (int i = tid; i < TDIM / 4; i += 256)
            ((float4*)prow)[i] = z;
        return;
    }

    float m = -3.402823466e+38f;
    for (int c = np + tid; c <= r; c += 256) m = fmaxf(m, prow[c]);
    red[tid] = m; __syncthreads();
    for (int s = 128; s > 0; s >>= 1) {
        if (tid < s) red[tid] = fmaxf(red[tid], red[tid + s]);
        __syncthreads();
    }
    m = red[0];
    __syncthreads();

    for (int c = tid; c < np; c += 256) prow[c] = 0.f;
    for (int c = r + 1 + tid; c < TDIM; c += 256) prow[c] = 0.f;
    float sum = 0.f;
    for (int c = np + tid; c <= r; c += 256) {
        float e = __expf(prow[c] - m);
        prow[c] = e;
        sum += e;
    }
    red[tid] = sum; __syncthreads();
    for (int s = 128; s > 0; s >>= 1) {
        if (tid < s) red[tid] += red[tid + s];
        __syncthreads();
    }
    const float inv = 1.0f / red[0];

    for (int c = np + tid; c <= r; c += 256) prow[c] *= inv;
}

// ---------------------------------------------------------------------------
// Kernel 4: y = P @ V  (NN), K-range clipped, 2-stage pipeline
// ---------------------------------------------------------------------------
__global__ __launch_bounds__(256, 2)
void k_gemm_pv(const int* __restrict__ n_padd_p, float* __restrict__ C)
{
    const int np = *n_padd_p;
    const int rm = blockIdx.y * BM;
    const int cn = blockIdx.x * BN;

    const int kstart = np & ~(BK - 1);
    const int kend   = rm + BM;
    const int nk = (kend > kstart) ? (kend - kstart) / BK : 0;

    extern __shared__ float sm[];
    float* As[2] = { sm,               sm + BM * SA };
    float* Bs[2] = { sm + 2 * BM * SA, sm + 2 * BM * SA + BK * SB };

    const int tid = threadIdx.x;
    const int lane = tid & 31, wid = tid >> 5;
    const int wm = wid & 1, wn = wid >> 1;
    const int g = lane >> 2, t4 = lane & 3;

    float acc[16][4];
    #pragma unroll
    for (int i = 0; i < 16; i++)
        #pragma unroll
        for (int j = 0; j < 4; j++) acc[i][j] = 0.f;

    if (nk > 0) {
        loadA_async(As[0], g_P + (size_t)rm * TDIM + kstart, TDIM, tid);
        loadB_async(Bs[0], g_qkv + (size_t)kstart * N3 + 2 * NF + cn, N3, tid);
        CP_COMMIT();
    }

    int buf = 0;
    for (int it = 0; it < nk; it++) {
        CP_WAIT0();
        __syncthreads();
        if (it + 1 < nk) {
            const int kn = kstart + (it + 1) * BK;
            loadA_async(As[buf ^ 1], g_P + (size_t)rm * TDIM + kn, TDIM, tid);
            loadB_async(Bs[buf ^ 1], g_qkv + (size_t)kn * N3 + 2 * NF + cn, N3, tid);
            CP_COMMIT();
        }
        compute_NN(As[buf], Bs[buf], acc, wm, wn, g, t4);
        buf ^= 1;
    }

    #pragma unroll
    for (int mt = 0; mt < 4; mt++) {
        #pragma unroll
        for (int nt = 0; nt < 4; nt++) {
            const int row = rm + wm * 64 + mt * 16 + g;
            const int col = cn + wn * 32 + nt * 8 + t4 * 2;
            *(float2*)(C + (size_t)row * NF + col) =
                make_float2(acc[mt*4+nt][0], acc[mt*4+nt][1]);
            *(float2*)(C + (size_t)(row + 8) * NF + col) =
                make_float2(acc[mt*4+nt][2], acc[mt*4+nt][3]);
        }
    }
}

// ---------------------------------------------------------------------------
extern "C" void kernel_launch(void* const* d_in, const int* in_sizes, int n_in,
                              void* d_out, int out_size)
{
    const float* x  = (const float*)d_in[0];
    const float* W  = (const float*)d_in[1];
    const float* b  = (const float*)d_in[2];
    const int*   np = (const int*)d_in[3];
    float* y = (float*)d_out;
    (void)in_sizes; (void)n_in; (void)out_size;

    const int smem_nn = 2 * (BM * SA + BK * SB) * (int)sizeof(float);  // 71680
    const int smem_nt = 4 * (BM * SA) * (int)sizeof(float);            // 73728

    cudaFuncSetAttribute(k_gemm_qkv, cudaFuncAttributeMaxDynamicSharedMemorySize, smem_nn);
    cudaFuncSetAttribute(k_gemm_s,   cudaFuncAttributeMaxDynamicSharedMemorySize, smem_nt);
    cudaFuncSetAttribute(k_gemm_pv,  cudaFuncAttributeMaxDynamicSharedMemorySize, smem_nn);

    dim3 t(256);
    dim3 grid_qkv(N3 / BN, TDIM / BM);
    dim3 grid_s(TDIM / BN, TDIM / BM);
    dim3 grid_pv(NF / BN, TDIM / BM);

    k_gemm_qkv<<<grid_qkv, t, smem_nn>>>(x, W, b);
    k_gemm_s<<<grid_s, t, smem_nt>>>(np);
    k_softmax<<<TDIM, t>>>(np);
    k_gemm_pv<<<grid_pv, t, smem_nn>>>(np, y);
}

// round 4
// speedup vs baseline: 1.1264x; 1.1264x over previous
#include <cuda_runtime.h>
#include <cuda_bf16.h>
#include <cstdint>
#include <math.h>

// Problem dims (fixed by the reference)
#define TDIM 4096
#define CDIM 2048
#define NF   2048
#define N3   6144   // 3*NF

#define BM 128
#define BN 128
#define BK 32
#define SA 36    // A-style tile stride in floats ([row][k]), conflict-free
#define SB 136   // B NN tile stride in floats ([k][n]), conflict-free

// Scratch (all fp32, values pre-rounded to tf32 grid where noted)
__device__ __align__(256) float g_qkv[(size_t)TDIM * N3];    // 96 MB (tf32-rounded)
__device__ __align__(256) float g_P[(size_t)TDIM * TDIM];    // 64 MB (tf32-rounded post-softmax)
__device__ __align__(256) float g_xr[(size_t)TDIM * CDIM];   // 32 MB (tf32-rounded x)
__device__ __align__(256) float g_wr[(size_t)CDIM * N3];     // 48 MB (tf32-rounded W)

__device__ __forceinline__ float f2tf32f(float x) {
    uint32_t u;
    asm("cvt.rna.tf32.f32 %0, %1;" : "=r"(u) : "f"(x));
    return __uint_as_float(u);
}

__device__ __forceinline__ void mma_tf32(float* d,
    uint32_t a0, uint32_t a1, uint32_t a2, uint32_t a3,
    uint32_t b0, uint32_t b1)
{
    asm volatile(
        "mma.sync.aligned.m16n8k8.row.col.f32.tf32.tf32.f32 "
        "{%0,%1,%2,%3}, {%4,%5,%6,%7}, {%8,%9}, {%0,%1,%2,%3};\n"
        : "+f"(d[0]), "+f"(d[1]), "+f"(d[2]), "+f"(d[3])
        : "r"(a0), "r"(a1), "r"(a2), "r"(a3), "r"(b0), "r"(b1));
}

__device__ __forceinline__ void cp16(float* smem_dst, const float* gsrc) {
    uint32_t s = (uint32_t)__cvta_generic_to_shared(smem_dst);
    asm volatile("cp.async.cg.shared.global [%0], [%1], 16;\n" :: "r"(s), "l"(gsrc));
}
#define CP_COMMIT() asm volatile("cp.async.commit_group;\n")
#define CP_WAIT0()  asm volatile("cp.async.wait_group 0;\n")

// ---------------------------------------------------------------------------
// Kernel 0: elementwise tf32 rounding pre-pass (src -> dst)
// ---------------------------------------------------------------------------
__global__ __launch_bounds__(256)
void k_round(const float* __restrict__ src, float* __restrict__ dst, int n4)
{
    int i = blockIdx.x * 256 + threadIdx.x;
    int stride = gridDim.x * 256;
    for (; i < n4; i += stride) {
        float4 v = ((const float4*)src)[i];
        v.x = f2tf32f(v.x); v.y = f2tf32f(v.y);
        v.z = f2tf32f(v.z); v.w = f2tf32f(v.w);
        ((float4*)dst)[i] = v;
    }
}

// Async-copy a 128x32 fp32 tile (row pitch ld) into tile[row][k], stride SA.
__device__ __forceinline__ void loadA_async(float* tile, const float* __restrict__ src,
                                            size_t ld, int tid)
{
    #pragma unroll
    for (int i = 0; i < 4; i++) {
        int idx = tid + i * 256;
        int r = idx >> 3;
        int k = (idx & 7) << 2;
        cp16(tile + r * SA + k, src + (size_t)r * ld + k);
    }
}

// Async-copy a 32x128 fp32 tile (row pitch ld) into tile[k][n], stride SB.
__device__ __forceinline__ void loadB_async(float* tile, const float* __restrict__ src,
                                            size_t ld, int tid)
{
    #pragma unroll
    for (int i = 0; i < 4; i++) {
        int idx = tid + i * 256;
        int k = idx >> 5;
        int n = (idx & 31) << 2;
        cp16(tile + k * SB + n, src + (size_t)k * ld + n);
    }
}

// Compute one 128x128x32 tile step; B tile stored [k][n] stride SB (NN case).
// Data is pre-rounded to the tf32 grid: feed raw bits to MMA.
__device__ __forceinline__ void compute_NN(const float* As, const float* Bs,
                                           float (*acc)[4], int wm, int wn, int g, int t4)
{
    #pragma unroll
    for (int ks = 0; ks < 4; ks++) {
        const int kb = ks * 8;
        uint32_t af[4][4], bf[4][2];
        #pragma unroll
        for (int mt = 0; mt < 4; mt++) {
            const int m = wm * 64 + mt * 16 + g;
            af[mt][0] = __float_as_uint(As[m * SA + kb + t4]);
            af[mt][1] = __float_as_uint(As[(m + 8) * SA + kb + t4]);
            af[mt][2] = __float_as_uint(As[m * SA + kb + t4 + 4]);
            af[mt][3] = __float_as_uint(As[(m + 8) * SA + kb + t4 + 4]);
        }
        #pragma unroll
        for (int nt = 0; nt < 4; nt++) {
            const int n = wn * 32 + nt * 8 + g;
            bf[nt][0] = __float_as_uint(Bs[(kb + t4) * SB + n]);
            bf[nt][1] = __float_as_uint(Bs[(kb + t4 + 4) * SB + n]);
        }
        #pragma unroll
        for (int mt = 0; mt < 4; mt++)
            #pragma unroll
            for (int nt = 0; nt < 4; nt++)
                mma_tf32(acc[mt * 4 + nt],
                         af[mt][0], af[mt][1], af[mt][2], af[mt][3],
                         bf[nt][0], bf[nt][1]);
    }
}

// Compute one tile step; B tile stored [n][k] stride SA (NT case, K rows).
__device__ __forceinline__ void compute_NT(const float* As, const float* Ks,
                                           float (*acc)[4], int wm, int wn, int g, int t4)
{
    #pragma unroll
    for (int ks = 0; ks < 4; ks++) {
        const int kb = ks * 8;
        uint32_t af[4][4], bf[4][2];
        #pragma unroll
        for (int mt = 0; mt < 4; mt++) {
            const int m = wm * 64 + mt * 16 + g;
            af[mt][0] = __float_as_uint(As[m * SA + kb + t4]);
            af[mt][1] = __float_as_uint(As[(m + 8) * SA + kb + t4]);
            af[mt][2] = __float_as_uint(As[m * SA + kb + t4 + 4]);
            af[mt][3] = __float_as_uint(As[(m + 8) * SA + kb + t4 + 4]);
        }
        #pragma unroll
        for (int nt = 0; nt < 4; nt++) {
            const int n = wn * 32 + nt * 8 + g;
            bf[nt][0] = __float_as_uint(Ks[n * SA + kb + t4]);
            bf[nt][1] = __float_as_uint(Ks[n * SA + kb + t4 + 4]);
        }
        #pragma unroll
        for (int mt = 0; mt < 4; mt++)
            #pragma unroll
            for (int nt = 0; nt < 4; nt++)
                mma_tf32(acc[mt * 4 + nt],
                         af[mt][0], af[mt][1], af[mt][2], af[mt][3],
                         bf[nt][0], bf[nt][1]);
    }
}

// ---------------------------------------------------------------------------
// Kernel 1: qkv = x @ W + b   (NN), 2-stage cp.async pipeline.
// Epilogue writes tf32-rounded values so downstream GEMMs need no cvt.
// ---------------------------------------------------------------------------
__global__ __launch_bounds__(256, 2)
void k_gemm_qkv(const float* __restrict__ A,   // g_xr (rounded)
                const float* __restrict__ B,   // g_wr (rounded)
                const float* __restrict__ bias)
{
    extern __shared__ float sm[];
    float* As[2] = { sm,               sm + BM * SA };
    float* Bs[2] = { sm + 2 * BM * SA, sm + 2 * BM * SA + BK * SB };

    const int tid = threadIdx.x;
    const int lane = tid & 31, wid = tid >> 5;
    const int wm = wid & 1, wn = wid >> 1;
    const int g = lane >> 2, t4 = lane & 3;
    const int m0 = blockIdx.y * BM;
    const int n0 = blockIdx.x * BN;

    float acc[16][4];
    #pragma unroll
    for (int i = 0; i < 16; i++)
        #pragma unroll
        for (int j = 0; j < 4; j++) acc[i][j] = 0.f;

    const int nk = CDIM / BK;
    loadA_async(As[0], A + (size_t)m0 * CDIM, CDIM, tid);
    loadB_async(Bs[0], B + n0, N3, tid);
    CP_COMMIT();

    int buf = 0;
    for (int it = 0; it < nk; it++) {
        CP_WAIT0();
        __syncthreads();
        if (it + 1 < nk) {
            const int kn = (it + 1) * BK;
            loadA_async(As[buf ^ 1], A + (size_t)m0 * CDIM + kn, CDIM, tid);
            loadB_async(Bs[buf ^ 1], B + (size_t)kn * N3 + n0, N3, tid);
            CP_COMMIT();
        }
        compute_NN(As[buf], Bs[buf], acc, wm, wn, g, t4);
        buf ^= 1;
    }

    #pragma unroll
    for (int mt = 0; mt < 4; mt++) {
        #pragma unroll
        for (int nt = 0; nt < 4; nt++) {
            const int row = m0 + wm * 64 + mt * 16 + g;
            const int col = n0 + wn * 32 + nt * 8 + t4 * 2;
            const float b0 = bias[col], b1 = bias[col + 1];
            *(float2*)(g_qkv + (size_t)row * N3 + col) =
                make_float2(f2tf32f(acc[mt*4+nt][0] + b0), f2tf32f(acc[mt*4+nt][1] + b1));
            *(float2*)(g_qkv + (size_t)(row + 8) * N3 + col) =
                make_float2(f2tf32f(acc[mt*4+nt][2] + b0), f2tf32f(acc[mt*4+nt][3] + b1));
        }
    }
}

// ---------------------------------------------------------------------------
// Kernel 2: S = scale * Q @ K^T (NT), masked-block skipping, 2-stage pipeline
// ---------------------------------------------------------------------------
__global__ __launch_bounds__(256, 2)
void k_gemm_s(const int* __restrict__ n_padd_p)
{
    const int np = *n_padd_p;
    const int rm = blockIdx.y * BM;
    const int cn = blockIdx.x * BN;
    if (cn >= rm + BM) return;
    if (cn + BN <= np) return;
    if (rm + BM <= np) return;

    extern __shared__ float sm[];
    float* As[2] = { sm,               sm + BM * SA };
    float* Ks[2] = { sm + 2 * BM * SA, sm + 3 * BM * SA };

    const int tid = threadIdx.x;
    const int lane = tid & 31, wid = tid >> 5;
    const int wm = wid & 1, wn = wid >> 1;
    const int g = lane >> 2, t4 = lane & 3;

    float acc[16][4];
    #pragma unroll
    for (int i = 0; i < 16; i++)
        #pragma unroll
        for (int j = 0; j < 4; j++) acc[i][j] = 0.f;

    const int nk = NF / BK;
    loadA_async(As[0], g_qkv + (size_t)rm * N3, N3, tid);
    loadA_async(Ks[0], g_qkv + (size_t)cn * N3 + NF, N3, tid);
    CP_COMMIT();

    int buf = 0;
    for (int it = 0; it < nk; it++) {
        CP_WAIT0();
        __syncthreads();
        if (it + 1 < nk) {
            const int kn = (it + 1) * BK;
            loadA_async(As[buf ^ 1], g_qkv + (size_t)rm * N3 + kn, N3, tid);
            loadA_async(Ks[buf ^ 1], g_qkv + (size_t)cn * N3 + NF + kn, N3, tid);
            CP_COMMIT();
        }
        compute_NT(As[buf], Ks[buf], acc, wm, wn, g, t4);
        buf ^= 1;
    }

    const float scale = rsqrtf((float)NF);
    #pragma unroll
    for (int mt = 0; mt < 4; mt++) {
        #pragma unroll
        for (int nt = 0; nt < 4; nt++) {
            const int row = rm + wm * 64 + mt * 16 + g;
            const int col = cn + wn * 32 + nt * 8 + t4 * 2;
            *(float2*)(g_P + (size_t)row * TDIM + col) =
                make_float2(acc[mt*4+nt][0] * scale, acc[mt*4+nt][1] * scale);
            *(float2*)(g_P + (size_t)(row + 8) * TDIM + col) =
                make_float2(acc[mt*4+nt][2] * scale, acc[mt*4+nt][3] * scale);
        }
    }
}

// ---------------------------------------------------------------------------
// Kernel 3: row softmax in-place on g_P; writes tf32-rounded probabilities.
// ---------------------------------------------------------------------------
__global__ __launch_bounds__(256)
void k_softmax(const int* __restrict__ n_padd_p)
{
    const int r = blockIdx.x;
    const int np = *n_padd_p;
    const int tid = threadIdx.x;
    __shared__ float red[256];

    float* prow = g_P + (size_t)r * TDIM;

    if (r < np) {
        float4 z = make_float4(0.f, 0.f, 0.f, 0.f);
        for (int i = tid; i < TDIM / 4; i += 256)
            ((float4*)prow)[i] = z;
        return;
    }

    float m = -3.402823466e+38f;
    for (int c = np + tid; c <= r; c += 256) m = fmaxf(m, prow[c]);
    red[tid] = m; __syncthreads();
    for (int s = 128; s > 0; s >>= 1) {
        if (tid < s) red[tid] = fmaxf(red[tid], red[tid + s]);
        __syncthreads();
    }
    m = red[0];
    __syncthreads();

    for (int c = tid; c < np; c += 256) prow[c] = 0.f;
    for (int c = r + 1 + tid; c < TDIM; c += 256) prow[c] = 0.f;
    float sum = 0.f;
    for (int c = np + tid; c <= r; c += 256) {
        float e = __expf(prow[c] - m);
        prow[c] = e;
        sum += e;
    }
    red[tid] = sum; __syncthreads();
    for (int s = 128; s > 0; s >>= 1) {
        if (tid < s) red[tid] += red[tid + s];
        __syncthreads();
    }
    const float inv = 1.0f / red[0];

    for (int c = np + tid; c <= r; c += 256) prow[c] = f2tf32f(prow[c] * inv);
}

// ---------------------------------------------------------------------------
// Kernel 4: y = P @ V  (NN), K-range clipped, 2-stage pipeline
// ---------------------------------------------------------------------------
__global__ __launch_bounds__(256, 2)
void k_gemm_pv(const int* __restrict__ n_padd_p, float* __restrict__ C)
{
    const int np = *n_padd_p;
    const int rm = blockIdx.y * BM;
    const int cn = blockIdx.x * BN;

    const int kstart = np & ~(BK - 1);
    const int kend   = rm + BM;
    const int nk = (kend > kstart) ? (kend - kstart) / BK : 0;

    extern __shared__ float sm[];
    float* As[2] = { sm,               sm + BM * SA };
    float* Bs[2] = { sm + 2 * BM * SA, sm + 2 * BM * SA + BK * SB };

    const int tid = threadIdx.x;
    const int lane = tid & 31, wid = tid >> 5;
    const int wm = wid & 1, wn = wid >> 1;
    const int g = lane >> 2, t4 = lane & 3;

    float acc[16][4];
    #pragma unroll
    for (int i = 0; i < 16; i++)
        #pragma unroll
        for (int j = 0; j < 4; j++) acc[i][j] = 0.f;

    if (nk > 0) {
        loadA_async(As[0], g_P + (size_t)rm * TDIM + kstart, TDIM, tid);
        loadB_async(Bs[0], g_qkv + (size_t)kstart * N3 + 2 * NF + cn, N3, tid);
        CP_COMMIT();
    }

    int buf = 0;
    for (int it = 0; it < nk; it++) {
        CP_WAIT0();
        __syncthreads();
        if (it + 1 < nk) {
            const int kn = kstart + (it + 1) * BK;
            loadA_async(As[buf ^ 1], g_P + (size_t)rm * TDIM + kn, TDIM, tid);
            loadB_async(Bs[buf ^ 1], g_qkv + (size_t)kn * N3 + 2 * NF + cn, N3, tid);
            CP_COMMIT();
        }
        compute_NN(As[buf], Bs[buf], acc, wm, wn, g, t4);
        buf ^= 1;
    }

    #pragma unroll
    for (int mt = 0; mt < 4; mt++) {
        #pragma unroll
        for (int nt = 0; nt < 4; nt++) {
            const int row = rm + wm * 64 + mt * 16 + g;
            const int col = cn + wn * 32 + nt * 8 + t4 * 2;
            *(float2*)(C + (size_t)row * NF + col) =
                make_float2(acc[mt*4+nt][0], acc[mt*4+nt][1]);
            *(float2*)(C + (size_t)(row + 8) * NF + col) =
                make_float2(acc[mt*4+nt][2], acc[mt*4+nt][3]);
        }
    }
}

// ---------------------------------------------------------------------------
extern "C" void kernel_launch(void* const* d_in, const int* in_sizes, int n_in,
                              void* d_out, int out_size)
{
    const float* x  = (const float*)d_in[0];
    const float* W  = (const float*)d_in[1];
    const float* b  = (const float*)d_in[2];
    const int*   np = (const int*)d_in[3];
    float* y = (float*)d_out;
    (void)in_sizes; (void)n_in; (void)out_size;

    const int smem_nn = 2 * (BM * SA + BK * SB) * (int)sizeof(float);  // 71680
    const int smem_nt = 4 * (BM * SA) * (int)sizeof(float);            // 73728

    cudaFuncSetAttribute(k_gemm_qkv, cudaFuncAttributeMaxDynamicSharedMemorySize, smem_nn);
    cudaFuncSetAttribute(k_gemm_s,   cudaFuncAttributeMaxDynamicSharedMemorySize, smem_nt);
    cudaFuncSetAttribute(k_gemm_pv,  cudaFuncAttributeMaxDynamicSharedMemorySize, smem_nn);

    float* xr; float* wr;
    cudaGetSymbolAddress((void**)&xr, g_xr);
    cudaGetSymbolAddress((void**)&wr, g_wr);

    dim3 t(256);
    dim3 grid_qkv(N3 / BN, TDIM / BM);
    dim3 grid_s(TDIM / BN, TDIM / BM);
    dim3 grid_pv(NF / BN, TDIM / BM);

    k_round<<<1024, t>>>(x, xr, TDIM * CDIM / 4);
    k_round<<<1024, t>>>(W, wr, CDIM * N3 / 4);
    k_gemm_qkv<<<grid_qkv, t, smem_nn>>>(xr, wr, b);
    k_gemm_s<<<grid_s, t, smem_nt>>>(np);
    k_softmax<<<TDIM, t>>>(np);
    k_gemm_pv<<<grid_pv, t, smem_nn>>>(np, y);
}